// round 16
// baseline (speedup 1.0000x reference)
#include <cuda_runtime.h>
#include <cuda_bf16.h>
#include <cstdint>
#include <cstddef>

// Problem constants
#define TB 2
#define TT 2048
#define TC 1024
#define TH 16
#define TD 64

// ---------------------------------------------------------------------------
// Scratch (__device__ globals; allocation-free rule)
// ---------------------------------------------------------------------------
__device__ __align__(256) __nv_bfloat16 g_qkvh[(size_t)TB * TT * 3 * TC];
__device__ __align__(256) __nv_bfloat16 g_qkvl[(size_t)TB * TT * 3 * TC];
__device__ __align__(256) __nv_bfloat16 g_xh[(size_t)TB * TT * TC];
__device__ __align__(256) __nv_bfloat16 g_xl[(size_t)TB * TT * TC];
__device__ __align__(256) __nv_bfloat16 g_wqh[(size_t)TC * 3 * TC];
__device__ __align__(256) __nv_bfloat16 g_wql[(size_t)TC * 3 * TC];
__device__ __align__(256) __nv_bfloat16 g_woh[(size_t)TC * TC];
__device__ __align__(256) __nv_bfloat16 g_wol[(size_t)TC * TC];
__device__ __align__(256) __nv_bfloat16 g_ah[(size_t)TB * TT * TC];
__device__ __align__(256) __nv_bfloat16 g_al[(size_t)TB * TT * TC];

// ---------------------------------------------------------------------------
__device__ __forceinline__ void split_pack(float x, float y,
                                           uint32_t& hi, uint32_t& lo)
{
    __nv_bfloat162 h = __float22bfloat162_rn(make_float2(x, y));
    float hx = __bfloat162float(h.x), hy = __bfloat162float(h.y);
    __nv_bfloat162 l = __float22bfloat162_rn(make_float2(x - hx, y - hy));
    hi = *(uint32_t*)&h;
    lo = *(uint32_t*)&l;
}

__device__ __forceinline__ void mma_bf16(float* d, const uint32_t* a,
                                         const uint32_t* b)
{
    asm volatile(
        "mma.sync.aligned.m16n8k16.row.col.f32.bf16.bf16.f32 "
        "{%0,%1,%2,%3}, {%4,%5,%6,%7}, {%8,%9}, {%0,%1,%2,%3};"
        : "+f"(d[0]), "+f"(d[1]), "+f"(d[2]), "+f"(d[3])
        : "r"(a[0]), "r"(a[1]), "r"(a[2]), "r"(a[3]), "r"(b[0]), "r"(b[1]));
}

// ---------------------------------------------------------------------------
// Fused split: x, Wqkv, Wout fp32 -> bf16 hi/lo planes, one launch.
// ---------------------------------------------------------------------------
__device__ __forceinline__ void split4(const float* __restrict__ in,
                                       __nv_bfloat16* __restrict__ hi,
                                       __nv_bfloat16* __restrict__ lo, int i)
{
    float4 v = *(const float4*)(in + i);
    uint32_t h0, l0, h1, l1;
    split_pack(v.x, v.y, h0, l0);
    split_pack(v.z, v.w, h1, l1);
    uint32_t* hp = (uint32_t*)(hi + i);
    uint32_t* lp = (uint32_t*)(lo + i);
    hp[0] = h0; hp[1] = h1;
    lp[0] = l0; lp[1] = l1;
}

#define NX  (TB * TT * TC)          // 4194304
#define NWQ (TC * 3 * TC)           // 3145728
#define NWO (TC * TC)               // 1048576

__global__ void split3_kernel(
    const float* __restrict__ x,  const float* __restrict__ wq,
    const float* __restrict__ wo,
    __nv_bfloat16* __restrict__ xh,  __nv_bfloat16* __restrict__ xl,
    __nv_bfloat16* __restrict__ wqh, __nv_bfloat16* __restrict__ wql,
    __nv_bfloat16* __restrict__ woh, __nv_bfloat16* __restrict__ wol)
{
    int i = (blockIdx.x * blockDim.x + threadIdx.x) * 4;
    if (i < NX) {
        split4(x, xh, xl, i);
    } else if (i < NX + NWQ) {
        split4(wq, wqh, wql, i - NX);
    } else if (i < NX + NWQ + NWO) {
        split4(wo, woh, wol, i - NX - NWQ);
    }
}

// ---------------------------------------------------------------------------
// Persistent split-bf16 GEMM (unchanged from round-15 pass).
// ---------------------------------------------------------------------------
#define CP_ASYNC16(dst, src) \
    asm volatile("cp.async.cg.shared.global [%0], [%1], 16;\n" :: "r"(dst), "l"(src))
#define CP_COMMIT() asm volatile("cp.async.commit_group;\n" ::)
#define CP_WAIT1()  asm volatile("cp.async.wait_group 1;\n" ::)
#define CP_WAIT0()  asm volatile("cp.async.wait_group 0;\n" ::)

__device__ __forceinline__ void gemm_load_stage(
    uint32_t sb, int tid, int row0, int col0, int k0, int K, int N,
    const __nv_bfloat16* __restrict__ Ah, const __nv_bfloat16* __restrict__ Al,
    const __nv_bfloat16* __restrict__ Bh, const __nv_bfloat16* __restrict__ Bl)
{
    #pragma unroll
    for (int i = 0; i < 2; i++) {
        int idx = tid + i * 256;
        int ra = idx >> 2, ca = idx & 3;
        uint32_t offa = ra * 64 + ((ca ^ (ra & 3)) << 4);
        size_t ga = (size_t)(row0 + ra) * K + k0 + ca * 8;
        CP_ASYNC16(sb + offa,        Ah + ga);
        CP_ASYNC16(sb + 8192 + offa, Al + ga);
        int rb = idx >> 4, cb = idx & 15;
        uint32_t offb = rb * 256 + ((cb ^ (rb & 7)) << 4);
        size_t gb = (size_t)(k0 + rb) * N + col0 + cb * 8;
        CP_ASYNC16(sb + 16384 + offb, Bh + gb);
        CP_ASYNC16(sb + 24576 + offb, Bl + gb);
    }
    CP_COMMIT();
}

extern __shared__ __align__(1024) char smem_raw[];

__global__ __launch_bounds__(256) void gemm_split_kernel(
    const __nv_bfloat16* __restrict__ Ah, const __nv_bfloat16* __restrict__ Al,
    const __nv_bfloat16* __restrict__ Bh, const __nv_bfloat16* __restrict__ Bl,
    float* __restrict__ C,
    __nv_bfloat16* __restrict__ Ch, __nv_bfloat16* __restrict__ Cl,
    int M, int N, int K, int mode)
{
    const int tid = threadIdx.x;
    const int warp = tid >> 5, lane = tid & 31;
    const int warpM = warp >> 2, warpN = warp & 3;
    const uint32_t smem_base = (uint32_t)__cvta_generic_to_shared(smem_raw);
    const int tiles_x = N >> 7;
    const int tiles = (M >> 7) * tiles_x;
    const int KT = K / 32;

    for (int t = blockIdx.x; t < tiles; t += gridDim.x) {
        const int row0 = (t / tiles_x) << 7;
        const int col0 = (t % tiles_x) << 7;

        __syncthreads();   // previous tile's smem fully consumed

        float acc[4][4][4];
        #pragma unroll
        for (int m = 0; m < 4; m++)
            #pragma unroll
            for (int n = 0; n < 4; n++)
                #pragma unroll
                for (int r = 0; r < 4; r++) acc[m][n][r] = 0.f;

        gemm_load_stage(smem_base,         tid, row0, col0, 0,  K, N, Ah, Al, Bh, Bl);
        gemm_load_stage(smem_base + 32768, tid, row0, col0, 32, K, N, Ah, Al, Bh, Bl);

        for (int kt = 0; kt < KT; kt++) {
            if (kt + 1 < KT) { CP_WAIT1(); } else { CP_WAIT0(); }
            __syncthreads();
            if (kt + 2 < KT)
                gemm_load_stage(smem_base + ((kt + 2) % 3) * 32768, tid,
                                row0, col0, (kt + 2) * 32, K, N, Ah, Al, Bh, Bl);
            const uint32_t sb = smem_base + (kt % 3) * 32768;

            #pragma unroll
            for (int ks = 0; ks < 2; ks++) {
                uint32_t bfr[2][4][2];
                const int rB = ks * 16 + (lane & 15);
                const int gB = lane >> 4;
                #pragma unroll
                for (int p = 0; p < 2; p++) {
                    #pragma unroll
                    for (int np = 0; np < 2; np++) {
                        const int chunk = warpN * 4 + np * 2 + gB;
                        uint32_t addr = sb + 16384 + p * 8192 + rB * 256
                                      + ((chunk ^ (rB & 7)) << 4);
                        asm volatile(
                            "ldmatrix.sync.aligned.m8n8.x4.trans.shared.b16 "
                            "{%0,%1,%2,%3}, [%4];"
                            : "=r"(bfr[p][np * 2][0]),     "=r"(bfr[p][np * 2][1]),
                              "=r"(bfr[p][np * 2 + 1][0]), "=r"(bfr[p][np * 2 + 1][1])
                            : "r"(addr));
                    }
                }
                #pragma unroll
                for (int m = 0; m < 4; m++) {
                    uint32_t afr[2][4];
                    const int rA = warpM * 64 + m * 16 + (lane & 15);
                    const int chA = ks * 2 + (lane >> 4);
                    #pragma unroll
                    for (int p = 0; p < 2; p++) {
                        uint32_t addr = sb + p * 8192 + rA * 64
                                      + ((chA ^ (rA & 3)) << 4);
                        asm volatile(
                            "ldmatrix.sync.aligned.m8n8.x4.shared.b16 {%0,%1,%2,%3}, [%4];"
                            : "=r"(afr[p][0]), "=r"(afr[p][1]),
                              "=r"(afr[p][2]), "=r"(afr[p][3]) : "r"(addr));
                    }
                    #pragma unroll
                    for (int n = 0; n < 4; n++) {
                        mma_bf16(acc[m][n], afr[0], bfr[0][n]);
                        mma_bf16(acc[m][n], afr[0], bfr[1][n]);
                        mma_bf16(acc[m][n], afr[1], bfr[0][n]);
                    }
                }
            }
        }

        #pragma unroll
        for (int m = 0; m < 4; m++) {
            #pragma unroll
            for (int n = 0; n < 4; n++) {
                const int r = row0 + warpM * 64 + m * 16 + (lane >> 2);
                const int c = col0 + warpN * 32 + n * 8 + (lane & 3) * 2;
                if (mode == 0) {
                    *(float2*)(C + (size_t)r * N + c) =
                        make_float2(acc[m][n][0], acc[m][n][1]);
                    *(float2*)(C + (size_t)(r + 8) * N + c) =
                        make_float2(acc[m][n][2], acc[m][n][3]);
                } else {
                    uint32_t h0, l0, h1, l1;
                    split_pack(acc[m][n][0], acc[m][n][1], h0, l0);
                    split_pack(acc[m][n][2], acc[m][n][3], h1, l1);
                    *(uint32_t*)(Ch + (size_t)r * N + c)       = h0;
                    *(uint32_t*)(Cl + (size_t)r * N + c)       = l0;
                    *(uint32_t*)(Ch + (size_t)(r + 8) * N + c) = h1;
                    *(uint32_t*)(Cl + (size_t)(r + 8) * N + c) = l1;
                }
            }
        }
    }
}

// ---------------------------------------------------------------------------
// Persistent tensor-core flash attention (causal), FULL 6-term numerics,
// now 256 threads (8 warps), each warp owns 16 q-rows -> 16 warps/SM.
//   scores = qh·kh + qh·kl + ql·kh
//   out    = ph·vh + pl·vh + ph·vl
// grid = 296. Snake-scheduled heavy-first tiles; tile = 128 q x 64 k.
// KV double-buffered (32KB stages: Kh@0 Kl@8K Vh@16K Vl@24K).
// smem: Qh[128][64] @0, Ql @16384, stages @32768 + s*32768.  96KB -> 2 CTA/SM.
// ---------------------------------------------------------------------------
__device__ __forceinline__ void attn_load_kv(
    uint32_t stage, int tid, int b, int h0, int j0,
    const __nv_bfloat16* __restrict__ qkvh,
    const __nv_bfloat16* __restrict__ qkvl)
{
    #pragma unroll
    for (int i = 0; i < 8; i++) {
        int idx = tid + i * 256;          // 0..2047
        int field = idx >> 9;             // 0:Kh 1:Kl 2:Vh 3:Vl
        int rem = idx & 511;
        int r = rem >> 3, ch = rem & 7;
        const __nv_bfloat16* src = (field & 1) ? qkvl : qkvh;
        int col = ((field >> 1) ? 2048 : 1024) + h0 * 64 + ch * 8;
        const __nv_bfloat16* gp = src + ((size_t)(b * TT + j0 + r)) * 3072 + col;
        uint32_t off = stage + field * 8192 + r * 128 + ((ch ^ (r & 7)) << 4);
        CP_ASYNC16(off, gp);
    }
}

#define ATT_NT 512   // 16 q-blocks * 32 (b,h)

__global__ __launch_bounds__(256) void attn_mma_kernel(
    const __nv_bfloat16* __restrict__ qkvh,
    const __nv_bfloat16* __restrict__ qkvl,
    __nv_bfloat16* __restrict__ outh, __nv_bfloat16* __restrict__ outl)
{
    const int tid = threadIdx.x;
    const int warp = tid >> 5, lane = tid & 31;
    const uint32_t smem_base = (uint32_t)__cvta_generic_to_shared(smem_raw);
    const int G = gridDim.x;

    for (int p = 0;; p++) {
        const int rk = p * G + ((p & 1) ? (G - 1 - (int)blockIdx.x)
                                        : (int)blockIdx.x);
        if (rk >= ATT_NT) break;
        const int qb = 15 - (rk >> 5);
        const int bh = rk & 31;
        const int b = bh >> 4;
        const int h0 = bh & 15;
        const int qbase = qb * 128;

        __syncthreads();   // previous tile's smem fully consumed

        // --- Q tile (both planes) + first KV stages ---
        #pragma unroll
        for (int i = 0; i < 8; i++) {
            int idx = tid + i * 256;      // 0..2047
            int plane = idx >> 10;
            int rem = idx & 1023;
            int r = rem >> 3, ch = rem & 7;
            const __nv_bfloat16* src = plane ? qkvl : qkvh;
            const __nv_bfloat16* gp =
                src + ((size_t)(b * TT + qbase + r)) * 3072 + h0 * 64 + ch * 8;
            uint32_t off = smem_base + plane * 16384 + r * 128
                         + ((ch ^ (r & 7)) << 4);
            CP_ASYNC16(off, gp);
        }
        const int nkb = 2 * (qb + 1);
        attn_load_kv(smem_base + 32768, tid, b, h0, 0, qkvh, qkvl);
        CP_COMMIT();
        attn_load_kv(smem_base + 65536, tid, b, h0, 64, qkvh, qkvl);
        CP_COMMIT();

        uint32_t qf[2][4][4];       // [plane][ktile][reg]  (warp's 16 rows)
        float o[8][4];
        float mrow[2], lrow[2];
        #pragma unroll
        for (int n = 0; n < 8; n++)
            #pragma unroll
            for (int c = 0; c < 4; c++) o[n][c] = 0.f;
        mrow[0] = mrow[1] = -3.0e38f;
        lrow[0] = lrow[1] = 0.f;

        const int rbase = qbase + warp * 16;

        for (int kb = 0; kb < nkb; kb++) {
            if (kb + 1 < nkb) { CP_WAIT1(); } else { CP_WAIT0(); }
            __syncthreads();

            if (kb == 0) {
                #pragma unroll
                for (int pp = 0; pp < 2; pp++) {
                    const int rA = warp * 16 + (lane & 15);
                    #pragma unroll
                    for (int kt = 0; kt < 4; kt++) {
                        const int ch = kt * 2 + (lane >> 4);
                        uint32_t addr = smem_base + pp * 16384 + rA * 128
                                      + ((ch ^ (rA & 7)) << 4);
                        asm volatile(
                            "ldmatrix.sync.aligned.m8n8.x4.shared.b16 "
                            "{%0,%1,%2,%3}, [%4];"
                            : "=r"(qf[pp][kt][0]), "=r"(qf[pp][kt][1]),
                              "=r"(qf[pp][kt][2]), "=r"(qf[pp][kt][3])
                            : "r"(addr));
                    }
                }
            }

            const uint32_t sk = smem_base + 32768 + (kb & 1) * 32768;
            const int j0 = kb * 64;

            float acc[8][4];
            #pragma unroll
            for (int n = 0; n < 8; n++)
                #pragma unroll
                for (int c = 0; c < 4; c++) acc[n][c] = 0.f;

            // ---- S = qh·Kh + qh·Kl + ql·Kh, x4 K loads (n-pairs) ----
            const int gK = lane >> 3;
            #pragma unroll
            for (int kt = 0; kt < 4; kt++) {
                #pragma unroll
                for (int np = 0; np < 4; np++) {
                    uint32_t kh[2][2], kl[2][2];
                    const int row = (np * 2 + (gK >> 1)) * 8 + (lane & 7);
                    const int ch = kt * 2 + (gK & 1);
                    uint32_t a0 = sk + row * 128 + ((ch ^ (row & 7)) << 4);
                    asm volatile(
                        "ldmatrix.sync.aligned.m8n8.x4.shared.b16 {%0,%1,%2,%3}, [%4];"
                        : "=r"(kh[0][0]), "=r"(kh[0][1]), "=r"(kh[1][0]), "=r"(kh[1][1])
                        : "r"(a0));
                    asm volatile(
                        "ldmatrix.sync.aligned.m8n8.x4.shared.b16 {%0,%1,%2,%3}, [%4];"
                        : "=r"(kl[0][0]), "=r"(kl[0][1]), "=r"(kl[1][0]), "=r"(kl[1][1])
                        : "r"(a0 + 8192));
                    #pragma unroll
                    for (int nn = 0; nn < 2; nn++) {
                        const int n = np * 2 + nn;
                        mma_bf16(acc[n], qf[0][kt], kh[nn]);
                        mma_bf16(acc[n], qf[0][kt], kl[nn]);
                        mma_bf16(acc[n], qf[1][kt], kh[nn]);
                    }
                }
            }

            const bool diag = (j0 >= qbase);
            #pragma unroll
            for (int n = 0; n < 8; n++)
                #pragma unroll
                for (int c = 0; c < 4; c++) {
                    float v = acc[n][c] * 0.125f;
                    if (diag) {
                        int col = j0 + n * 8 + ((lane & 3) << 1) + (c & 1);
                        int row = rbase + (lane >> 2) + ((c >> 1) << 3);
                        if (col > row) v = -1e30f;
                    }
                    acc[n][c] = v;
                }

            #pragma unroll
            for (int h = 0; h < 2; h++) {
                float mt = mrow[h];
                #pragma unroll
                for (int n = 0; n < 8; n++)
                    mt = fmaxf(mt, fmaxf(acc[n][2 * h], acc[n][2 * h + 1]));
                mt = fmaxf(mt, __shfl_xor_sync(0xffffffffu, mt, 1));
                mt = fmaxf(mt, __shfl_xor_sync(0xffffffffu, mt, 2));
                float rs = __expf(mrow[h] - mt);
                mrow[h] = mt;
                float lsum = 0.f;
                #pragma unroll
                for (int n = 0; n < 8; n++) {
                    float p0 = __expf(acc[n][2 * h]     - mt);
                    float p1 = __expf(acc[n][2 * h + 1] - mt);
                    acc[n][2 * h]     = p0;
                    acc[n][2 * h + 1] = p1;
                    lsum += p0 + p1;
                    o[n][2 * h]     *= rs;
                    o[n][2 * h + 1] *= rs;
                }
                lrow[h] = lrow[h] * rs + lsum;
            }

            // ---- O += ph·Vh + pl·Vh + ph·Vl, x4.trans V loads (n-pairs) ----
            #pragma unroll
            for (int kt = 0; kt < 4; kt++) {
                uint32_t pah[4], pal[4];
                split_pack(acc[2 * kt][0],     acc[2 * kt][1],     pah[0], pal[0]);
                split_pack(acc[2 * kt][2],     acc[2 * kt][3],     pah[1], pal[1]);
                split_pack(acc[2 * kt + 1][0], acc[2 * kt + 1][1], pah[2], pal[2]);
                split_pack(acc[2 * kt + 1][2], acc[2 * kt + 1][3], pah[3], pal[3]);
                const int rV = kt * 16 + (lane & 15);
                const int gV = lane >> 4;
                #pragma unroll
                for (int np = 0; np < 4; np++) {
                    uint32_t vh[2][2], vl[2][2];
                    const int ch = np * 2 + gV;
                    uint32_t a0 = sk + 16384 + rV * 128 + ((ch ^ (rV & 7)) << 4);
                    asm volatile(
                        "ldmatrix.sync.aligned.m8n8.x4.trans.shared.b16 {%0,%1,%2,%3}, [%4];"
                        : "=r"(vh[0][0]), "=r"(vh[0][1]), "=r"(vh[1][0]), "=r"(vh[1][1])
                        : "r"(a0));
                    asm volatile(
                        "ldmatrix.sync.aligned.m8n8.x4.trans.shared.b16 {%0,%1,%2,%3}, [%4];"
                        : "=r"(vl[0][0]), "=r"(vl[0][1]), "=r"(vl[1][0]), "=r"(vl[1][1])
                        : "r"(a0 + 8192));
                    #pragma unroll
                    for (int nn = 0; nn < 2; nn++) {
                        const int n = np * 2 + nn;
                        mma_bf16(o[n], pah, vh[nn]);
                        mma_bf16(o[n], pal, vh[nn]);
                        mma_bf16(o[n], pah, vl[nn]);
                    }
                }
            }

            __syncthreads();
            if (kb + 2 < nkb) {
                attn_load_kv(smem_base + 32768 + (kb & 1) * 32768, tid, b, h0,
                             (kb + 2) * 64, qkvh, qkvl);
                CP_COMMIT();
            }
        }

        float inv[2];
        #pragma unroll
        for (int h = 0; h < 2; h++) {
            float lt = lrow[h];
            lt += __shfl_xor_sync(0xffffffffu, lt, 1);
            lt += __shfl_xor_sync(0xffffffffu, lt, 2);
            inv[h] = 1.f / lt;
        }

        const int r0 = rbase + (lane >> 2);
        #pragma unroll
        for (int n = 0; n < 8; n++) {
            const int cd = h0 * 64 + n * 8 + ((lane & 3) << 1);
            uint32_t h_, l_;
            split_pack(o[n][0] * inv[0], o[n][1] * inv[0], h_, l_);
            size_t base0 = (size_t)(b * TT + r0) * 1024 + cd;
            *(uint32_t*)(outh + base0) = h_;
            *(uint32_t*)(outl + base0) = l_;
            split_pack(o[n][2] * inv[1], o[n][3] * inv[1], h_, l_);
            size_t base1 = (size_t)(b * TT + r0 + 8) * 1024 + cd;
            *(uint32_t*)(outh + base1) = h_;
            *(uint32_t*)(outl + base1) = l_;
        }
    }
}

// ---------------------------------------------------------------------------
extern "C" void kernel_launch(void* const* d_in, const int* in_sizes, int n_in,
                              void* d_out, int out_size)
{
    const float* x    = (const float*)d_in[0];
    const float* Wqkv = (const float*)d_in[1];
    const float* Wout = (const float*)d_in[2];
    float* out = (float*)d_out;

    __nv_bfloat16 *qkvh, *qkvl, *xh, *xl, *wqh, *wql, *woh, *wol, *ah, *al;
    cudaGetSymbolAddress((void**)&qkvh, g_qkvh); cudaGetSymbolAddress((void**)&qkvl, g_qkvl);
    cudaGetSymbolAddress((void**)&xh, g_xh);     cudaGetSymbolAddress((void**)&xl, g_xl);
    cudaGetSymbolAddress((void**)&wqh, g_wqh);   cudaGetSymbolAddress((void**)&wql, g_wql);
    cudaGetSymbolAddress((void**)&woh, g_woh);   cudaGetSymbolAddress((void**)&wol, g_wol);
    cudaGetSymbolAddress((void**)&ah, g_ah);     cudaGetSymbolAddress((void**)&al, g_al);

    cudaFuncSetAttribute(gemm_split_kernel,
                         cudaFuncAttributeMaxDynamicSharedMemorySize, 98304);
    cudaFuncSetAttribute(attn_mma_kernel,
                         cudaFuncAttributeMaxDynamicSharedMemorySize, 98304);

    const int M = TB * TT;            // 4096
    const int total4 = (NX + NWQ + NWO) / 4;

    // 0) fused input splits
    split3_kernel<<<(total4 + 255) / 256, 256>>>(x, Wqkv, Wout,
                                                 xh, xl, wqh, wql, woh, wol);

    // 1) QKV projection -> bf16 hi/lo planes (persistent, 768 tiles)
    {
        int tiles = (M / 128) * (3 * TC / 128);
        int grid = tiles < 296 ? tiles : 296;
        gemm_split_kernel<<<grid, 256, 98304>>>(
            xh, xl, wqh, wql, nullptr, qkvh, qkvl, M, 3 * TC, TC, 1);
    }

    // 2) Persistent causal flash attention (8 warps/CTA) -> bf16 hi/lo planes
    attn_mma_kernel<<<296, 256, 98304>>>(qkvh, qkvl, ah, al);

    // 3) Output projection -> fp32 out (256 tiles)
    {
        int tiles = (M / 128) * (TC / 128);
        int grid = tiles < 296 ? tiles : 296;
        gemm_split_kernel<<<grid, 256, 98304>>>(
            ah, al, woh, wol, out, nullptr, nullptr, M, TC, TC, 0);
    }
}

// round 17
// speedup vs baseline: 1.4010x; 1.4010x over previous
#include <cuda_runtime.h>
#include <cuda_bf16.h>
#include <cstdint>
#include <cstddef>

// Problem constants
#define TB 2
#define TT 2048
#define TC 1024
#define TH 16
#define TD 64

// ---------------------------------------------------------------------------
// Scratch (__device__ globals; allocation-free rule)
// ---------------------------------------------------------------------------
__device__ __align__(256) __nv_bfloat16 g_qkvh[(size_t)TB * TT * 3 * TC];
__device__ __align__(256) __nv_bfloat16 g_qkvl[(size_t)TB * TT * 3 * TC];
__device__ __align__(256) __nv_bfloat16 g_xh[(size_t)TB * TT * TC];
__device__ __align__(256) __nv_bfloat16 g_xl[(size_t)TB * TT * TC];
__device__ __align__(256) __nv_bfloat16 g_wqh[(size_t)TC * 3 * TC];
__device__ __align__(256) __nv_bfloat16 g_wql[(size_t)TC * 3 * TC];
__device__ __align__(256) __nv_bfloat16 g_woh[(size_t)TC * TC];
__device__ __align__(256) __nv_bfloat16 g_wol[(size_t)TC * TC];
__device__ __align__(256) __nv_bfloat16 g_ah[(size_t)TB * TT * TC];
__device__ __align__(256) __nv_bfloat16 g_al[(size_t)TB * TT * TC];

// ---------------------------------------------------------------------------
__device__ __forceinline__ void split_pack(float x, float y,
                                           uint32_t& hi, uint32_t& lo)
{
    __nv_bfloat162 h = __float22bfloat162_rn(make_float2(x, y));
    float hx = __bfloat162float(h.x), hy = __bfloat162float(h.y);
    __nv_bfloat162 l = __float22bfloat162_rn(make_float2(x - hx, y - hy));
    hi = *(uint32_t*)&h;
    lo = *(uint32_t*)&l;
}

__device__ __forceinline__ void mma_bf16(float* d, const uint32_t* a,
                                         const uint32_t* b)
{
    asm volatile(
        "mma.sync.aligned.m16n8k16.row.col.f32.bf16.bf16.f32 "
        "{%0,%1,%2,%3}, {%4,%5,%6,%7}, {%8,%9}, {%0,%1,%2,%3};"
        : "+f"(d[0]), "+f"(d[1]), "+f"(d[2]), "+f"(d[3])
        : "r"(a[0]), "r"(a[1]), "r"(a[2]), "r"(a[3]), "r"(b[0]), "r"(b[1]));
}

// ---------------------------------------------------------------------------
// Fused split: x, Wqkv, Wout fp32 -> bf16 hi/lo planes, one launch.
// ---------------------------------------------------------------------------
__device__ __forceinline__ void split4(const float* __restrict__ in,
                                       __nv_bfloat16* __restrict__ hi,
                                       __nv_bfloat16* __restrict__ lo, int i)
{
    float4 v = *(const float4*)(in + i);
    uint32_t h0, l0, h1, l1;
    split_pack(v.x, v.y, h0, l0);
    split_pack(v.z, v.w, h1, l1);
    uint32_t* hp = (uint32_t*)(hi + i);
    uint32_t* lp = (uint32_t*)(lo + i);
    hp[0] = h0; hp[1] = h1;
    lp[0] = l0; lp[1] = l1;
}

#define NX  (TB * TT * TC)          // 4194304
#define NWQ (TC * 3 * TC)           // 3145728
#define NWO (TC * TC)               // 1048576

__global__ void split3_kernel(
    const float* __restrict__ x,  const float* __restrict__ wq,
    const float* __restrict__ wo,
    __nv_bfloat16* __restrict__ xh,  __nv_bfloat16* __restrict__ xl,
    __nv_bfloat16* __restrict__ wqh, __nv_bfloat16* __restrict__ wql,
    __nv_bfloat16* __restrict__ woh, __nv_bfloat16* __restrict__ wol)
{
    int i = (blockIdx.x * blockDim.x + threadIdx.x) * 4;
    if (i < NX) {
        split4(x, xh, xl, i);
    } else if (i < NX + NWQ) {
        split4(wq, wqh, wql, i - NX);
    } else if (i < NX + NWQ + NWO) {
        split4(wo, woh, wol, i - NX - NWQ);
    }
}

// ---------------------------------------------------------------------------
// Persistent split-bf16 GEMM (unchanged round-15 pass: 451us config).
// ---------------------------------------------------------------------------
#define CP_ASYNC16(dst, src) \
    asm volatile("cp.async.cg.shared.global [%0], [%1], 16;\n" :: "r"(dst), "l"(src))
#define CP_COMMIT() asm volatile("cp.async.commit_group;\n" ::)
#define CP_WAIT1()  asm volatile("cp.async.wait_group 1;\n" ::)
#define CP_WAIT0()  asm volatile("cp.async.wait_group 0;\n" ::)

__device__ __forceinline__ void gemm_load_stage(
    uint32_t sb, int tid, int row0, int col0, int k0, int K, int N,
    const __nv_bfloat16* __restrict__ Ah, const __nv_bfloat16* __restrict__ Al,
    const __nv_bfloat16* __restrict__ Bh, const __nv_bfloat16* __restrict__ Bl)
{
    #pragma unroll
    for (int i = 0; i < 2; i++) {
        int idx = tid + i * 256;
        int ra = idx >> 2, ca = idx & 3;
        uint32_t offa = ra * 64 + ((ca ^ (ra & 3)) << 4);
        size_t ga = (size_t)(row0 + ra) * K + k0 + ca * 8;
        CP_ASYNC16(sb + offa,        Ah + ga);
        CP_ASYNC16(sb + 8192 + offa, Al + ga);
        int rb = idx >> 4, cb = idx & 15;
        uint32_t offb = rb * 256 + ((cb ^ (rb & 7)) << 4);
        size_t gb = (size_t)(k0 + rb) * N + col0 + cb * 8;
        CP_ASYNC16(sb + 16384 + offb, Bh + gb);
        CP_ASYNC16(sb + 24576 + offb, Bl + gb);
    }
    CP_COMMIT();
}

extern __shared__ __align__(1024) char smem_raw[];

__global__ __launch_bounds__(256) void gemm_split_kernel(
    const __nv_bfloat16* __restrict__ Ah, const __nv_bfloat16* __restrict__ Al,
    const __nv_bfloat16* __restrict__ Bh, const __nv_bfloat16* __restrict__ Bl,
    float* __restrict__ C,
    __nv_bfloat16* __restrict__ Ch, __nv_bfloat16* __restrict__ Cl,
    int M, int N, int K, int mode)
{
    const int tid = threadIdx.x;
    const int warp = tid >> 5, lane = tid & 31;
    const int warpM = warp >> 2, warpN = warp & 3;
    const uint32_t smem_base = (uint32_t)__cvta_generic_to_shared(smem_raw);
    const int tiles_x = N >> 7;
    const int tiles = (M >> 7) * tiles_x;
    const int KT = K / 32;

    for (int t = blockIdx.x; t < tiles; t += gridDim.x) {
        const int row0 = (t / tiles_x) << 7;
        const int col0 = (t % tiles_x) << 7;

        __syncthreads();   // previous tile's smem fully consumed

        float acc[4][4][4];
        #pragma unroll
        for (int m = 0; m < 4; m++)
            #pragma unroll
            for (int n = 0; n < 4; n++)
                #pragma unroll
                for (int r = 0; r < 4; r++) acc[m][n][r] = 0.f;

        gemm_load_stage(smem_base,         tid, row0, col0, 0,  K, N, Ah, Al, Bh, Bl);
        gemm_load_stage(smem_base + 32768, tid, row0, col0, 32, K, N, Ah, Al, Bh, Bl);

        for (int kt = 0; kt < KT; kt++) {
            if (kt + 1 < KT) { CP_WAIT1(); } else { CP_WAIT0(); }
            __syncthreads();
            if (kt + 2 < KT)
                gemm_load_stage(smem_base + ((kt + 2) % 3) * 32768, tid,
                                row0, col0, (kt + 2) * 32, K, N, Ah, Al, Bh, Bl);
            const uint32_t sb = smem_base + (kt % 3) * 32768;

            #pragma unroll
            for (int ks = 0; ks < 2; ks++) {
                uint32_t bfr[2][4][2];
                const int rB = ks * 16 + (lane & 15);
                const int gB = lane >> 4;
                #pragma unroll
                for (int p = 0; p < 2; p++) {
                    #pragma unroll
                    for (int np = 0; np < 2; np++) {
                        const int chunk = warpN * 4 + np * 2 + gB;
                        uint32_t addr = sb + 16384 + p * 8192 + rB * 256
                                      + ((chunk ^ (rB & 7)) << 4);
                        asm volatile(
                            "ldmatrix.sync.aligned.m8n8.x4.trans.shared.b16 "
                            "{%0,%1,%2,%3}, [%4];"
                            : "=r"(bfr[p][np * 2][0]),     "=r"(bfr[p][np * 2][1]),
                              "=r"(bfr[p][np * 2 + 1][0]), "=r"(bfr[p][np * 2 + 1][1])
                            : "r"(addr));
                    }
                }
                #pragma unroll
                for (int m = 0; m < 4; m++) {
                    uint32_t afr[2][4];
                    const int rA = warpM * 64 + m * 16 + (lane & 15);
                    const int chA = ks * 2 + (lane >> 4);
                    #pragma unroll
                    for (int p = 0; p < 2; p++) {
                        uint32_t addr = sb + p * 8192 + rA * 64
                                      + ((chA ^ (rA & 3)) << 4);
                        asm volatile(
                            "ldmatrix.sync.aligned.m8n8.x4.shared.b16 {%0,%1,%2,%3}, [%4];"
                            : "=r"(afr[p][0]), "=r"(afr[p][1]),
                              "=r"(afr[p][2]), "=r"(afr[p][3]) : "r"(addr));
                    }
                    #pragma unroll
                    for (int n = 0; n < 4; n++) {
                        mma_bf16(acc[m][n], afr[0], bfr[0][n]);
                        mma_bf16(acc[m][n], afr[0], bfr[1][n]);
                        mma_bf16(acc[m][n], afr[1], bfr[0][n]);
                    }
                }
            }
        }

        #pragma unroll
        for (int m = 0; m < 4; m++) {
            #pragma unroll
            for (int n = 0; n < 4; n++) {
                const int r = row0 + warpM * 64 + m * 16 + (lane >> 2);
                const int c = col0 + warpN * 32 + n * 8 + (lane & 3) * 2;
                if (mode == 0) {
                    *(float2*)(C + (size_t)r * N + c) =
                        make_float2(acc[m][n][0], acc[m][n][1]);
                    *(float2*)(C + (size_t)(r + 8) * N + c) =
                        make_float2(acc[m][n][2], acc[m][n][3]);
                } else {
                    uint32_t h0, l0, h1, l1;
                    split_pack(acc[m][n][0], acc[m][n][1], h0, l0);
                    split_pack(acc[m][n][2], acc[m][n][3], h1, l1);
                    *(uint32_t*)(Ch + (size_t)r * N + c)       = h0;
                    *(uint32_t*)(Cl + (size_t)r * N + c)       = l0;
                    *(uint32_t*)(Ch + (size_t)(r + 8) * N + c) = h1;
                    *(uint32_t*)(Cl + (size_t)(r + 8) * N + c) = l1;
                }
            }
        }
    }
}

// ---------------------------------------------------------------------------
// Persistent tensor-core flash attention (causal), FULL 6-term numerics,
// round-15 structure (4 warps x 2 m-tiles) with INTERLEAVED row mapping:
//   warp w, m-tile m -> rows [w*16 + m*64, +16)   (balances causal masking)
// and exact skips of fully-masked S-tiles / P-tiles in diagonal key-blocks
// (skipped S tiles are overwritten to -1e30 by the mask pass; skipped P
// tiles are exactly zero since __expf(-1e30 - mt) == 0 -> bit-identical).
// grid = 296, block = 128. Snake-scheduled heavy-first tiles.
// KV double-buffered (32KB stages: Kh@0 Kl@8K Vh@16K Vl@24K).
// smem: Qh[128][64] @0, Ql @16384, stages @32768 + s*32768.  96KB -> 2 CTA/SM.
// ---------------------------------------------------------------------------
__device__ __forceinline__ void attn_load_kv(
    uint32_t stage, int tid, int b, int h0, int j0,
    const __nv_bfloat16* __restrict__ qkvh,
    const __nv_bfloat16* __restrict__ qkvl)
{
    #pragma unroll
    for (int i = 0; i < 16; i++) {
        int idx = tid + i * 128;
        int field = idx >> 9;             // 0:Kh 1:Kl 2:Vh 3:Vl
        int rem = idx & 511;
        int r = rem >> 3, ch = rem & 7;
        const __nv_bfloat16* src = (field & 1) ? qkvl : qkvh;
        int col = ((field >> 1) ? 2048 : 1024) + h0 * 64 + ch * 8;
        const __nv_bfloat16* gp = src + ((size_t)(b * TT + j0 + r)) * 3072 + col;
        uint32_t off = stage + field * 8192 + r * 128 + ((ch ^ (r & 7)) << 4);
        CP_ASYNC16(off, gp);
    }
}

#define ATT_NT 512   // 16 q-blocks * 32 (b,h)

__global__ __launch_bounds__(128) void attn_mma_kernel(
    const __nv_bfloat16* __restrict__ qkvh,
    const __nv_bfloat16* __restrict__ qkvl,
    __nv_bfloat16* __restrict__ outh, __nv_bfloat16* __restrict__ outl)
{
    const int tid = threadIdx.x;
    const int warp = tid >> 5, lane = tid & 31;
    const uint32_t smem_base = (uint32_t)__cvta_generic_to_shared(smem_raw);
    const int G = gridDim.x;

    for (int p = 0;; p++) {
        const int rk = p * G + ((p & 1) ? (G - 1 - (int)blockIdx.x)
                                        : (int)blockIdx.x);
        if (rk >= ATT_NT) break;
        const int qb = 15 - (rk >> 5);
        const int bh = rk & 31;
        const int b = bh >> 4;
        const int h0 = bh & 15;
        const int qbase = qb * 128;

        __syncthreads();   // previous tile's smem fully consumed

        // --- Q tile (both planes) + first KV stages ---
        #pragma unroll
        for (int i = 0; i < 16; i++) {
            int idx = tid + i * 128;
            int plane = idx >> 10;
            int rem = idx & 1023;
            int r = rem >> 3, ch = rem & 7;
            const __nv_bfloat16* src = plane ? qkvl : qkvh;
            const __nv_bfloat16* gp =
                src + ((size_t)(b * TT + qbase + r)) * 3072 + h0 * 64 + ch * 8;
            uint32_t off = smem_base + plane * 16384 + r * 128
                         + ((ch ^ (r & 7)) << 4);
            CP_ASYNC16(off, gp);
        }
        const int nkb = 2 * (qb + 1);
        attn_load_kv(smem_base + 32768, tid, b, h0, 0, qkvh, qkvl);
        CP_COMMIT();
        attn_load_kv(smem_base + 65536, tid, b, h0, 64, qkvh, qkvl);
        CP_COMMIT();

        uint32_t qf[2][2][4][4];      // [plane][m][kt][reg]
        float o[2][8][4];
        float mrow[2][2], lrow[2][2];
        #pragma unroll
        for (int m = 0; m < 2; m++) {
            #pragma unroll
            for (int n = 0; n < 8; n++)
                #pragma unroll
                for (int c = 0; c < 4; c++) o[m][n][c] = 0.f;
            mrow[m][0] = mrow[m][1] = -3.0e38f;
            lrow[m][0] = lrow[m][1] = 0.f;
        }

        // Interleaved m-tile row bases (relative to qbase)
        const int rb0 = warp * 16;          // m=0 rows
        const int rb1 = warp * 16 + 64;     // m=1 rows

        for (int kb = 0; kb < nkb; kb++) {
            if (kb + 1 < nkb) { CP_WAIT1(); } else { CP_WAIT0(); }
            __syncthreads();

            if (kb == 0) {
                #pragma unroll
                for (int pp = 0; pp < 2; pp++)
                    #pragma unroll
                    for (int m = 0; m < 2; m++) {
                        const int rA = warp * 16 + m * 64 + (lane & 15);
                        #pragma unroll
                        for (int kt = 0; kt < 4; kt++) {
                            const int ch = kt * 2 + (lane >> 4);
                            uint32_t addr = smem_base + pp * 16384 + rA * 128
                                          + ((ch ^ (rA & 7)) << 4);
                            asm volatile(
                                "ldmatrix.sync.aligned.m8n8.x4.shared.b16 "
                                "{%0,%1,%2,%3}, [%4];"
                                : "=r"(qf[pp][m][kt][0]), "=r"(qf[pp][m][kt][1]),
                                  "=r"(qf[pp][m][kt][2]), "=r"(qf[pp][m][kt][3])
                                : "r"(addr));
                        }
                    }
            }

            const uint32_t sk = smem_base + 32768 + (kb & 1) * 32768;
            const int j0 = kb * 64;
            const int jrel = j0 - qbase;    // key col base relative to q tile
            const bool diag = (jrel >= 0);

            float acc[2][8][4];
            #pragma unroll
            for (int m = 0; m < 2; m++)
                #pragma unroll
                for (int n = 0; n < 8; n++)
                    #pragma unroll
                    for (int c = 0; c < 4; c++) acc[m][n][c] = 0.f;

            // ---- S = qh·Kh + qh·Kl + ql·Kh, x4 K loads (n-pairs) ----
            const int gK = lane >> 3;
            #pragma unroll
            for (int kt = 0; kt < 4; kt++) {
                #pragma unroll
                for (int np = 0; np < 4; np++) {
                    // pair fully masked for BOTH m-tiles (m1 has higher rows)?
                    if (diag && jrel + np * 16 > rb1 + 15) continue;
                    uint32_t kh[2][2], kl[2][2];
                    const int row = (np * 2 + (gK >> 1)) * 8 + (lane & 7);
                    const int ch = kt * 2 + (gK & 1);
                    uint32_t a0 = sk + row * 128 + ((ch ^ (row & 7)) << 4);
                    asm volatile(
                        "ldmatrix.sync.aligned.m8n8.x4.shared.b16 {%0,%1,%2,%3}, [%4];"
                        : "=r"(kh[0][0]), "=r"(kh[0][1]), "=r"(kh[1][0]), "=r"(kh[1][1])
                        : "r"(a0));
                    asm volatile(
                        "ldmatrix.sync.aligned.m8n8.x4.shared.b16 {%0,%1,%2,%3}, [%4];"
                        : "=r"(kl[0][0]), "=r"(kl[0][1]), "=r"(kl[1][0]), "=r"(kl[1][1])
                        : "r"(a0 + 8192));
                    #pragma unroll
                    for (int nn = 0; nn < 2; nn++) {
                        const int n = np * 2 + nn;
                        const int colb = jrel + n * 8;
                        #pragma unroll
                        for (int m = 0; m < 2; m++) {
                            const int rbm = (m == 0) ? rb0 : rb1;
                            if (diag && colb > rbm + 15) continue;  // fully masked
                            mma_bf16(acc[m][n], qf[0][m][kt], kh[nn]);
                            mma_bf16(acc[m][n], qf[0][m][kt], kl[nn]);
                            mma_bf16(acc[m][n], qf[1][m][kt], kh[nn]);
                        }
                    }
                }
            }

            #pragma unroll
            for (int m = 0; m < 2; m++) {
                const int rbm = (m == 0) ? rb0 : rb1;
                #pragma unroll
                for (int n = 0; n < 8; n++)
                    #pragma unroll
                    for (int c = 0; c < 4; c++) {
                        float v = acc[m][n][c] * 0.125f;
                        if (diag) {
                            int col = jrel + n * 8 + ((lane & 3) << 1) + (c & 1);
                            int row = rbm + (lane >> 2) + ((c >> 1) << 3);
                            if (col > row) v = -1e30f;
                        }
                        acc[m][n][c] = v;
                    }
            }

            #pragma unroll
            for (int m = 0; m < 2; m++) {
                #pragma unroll
                for (int h = 0; h < 2; h++) {
                    float mt = mrow[m][h];
                    #pragma unroll
                    for (int n = 0; n < 8; n++)
                        mt = fmaxf(mt, fmaxf(acc[m][n][2 * h], acc[m][n][2 * h + 1]));
                    mt = fmaxf(mt, __shfl_xor_sync(0xffffffffu, mt, 1));
                    mt = fmaxf(mt, __shfl_xor_sync(0xffffffffu, mt, 2));
                    float rs = __expf(mrow[m][h] - mt);
                    mrow[m][h] = mt;
                    float lsum = 0.f;
                    #pragma unroll
                    for (int n = 0; n < 8; n++) {
                        float p0 = __expf(acc[m][n][2 * h]     - mt);
                        float p1 = __expf(acc[m][n][2 * h + 1] - mt);
                        acc[m][n][2 * h]     = p0;
                        acc[m][n][2 * h + 1] = p1;
                        lsum += p0 + p1;
                        o[m][n][2 * h]     *= rs;
                        o[m][n][2 * h + 1] *= rs;
                    }
                    lrow[m][h] = lrow[m][h] * rs + lsum;
                }
            }

            // ---- O += ph·Vh + pl·Vh + ph·Vl, x4.trans V loads (n-pairs) ----
            #pragma unroll
            for (int kt = 0; kt < 4; kt++) {
                const int colb = jrel + kt * 16;     // P-tile key base
                // Both m-tiles fully masked -> whole kt is exact zero: skip.
                if (diag && colb > rb1 + 15) continue;
                const bool skip0 = diag && colb > rb0 + 15;  // m0 P-tile zero
                uint32_t pah[2][4], pal[2][4];
                #pragma unroll
                for (int m = 0; m < 2; m++) {
                    if (m == 0 && skip0) continue;
                    split_pack(acc[m][2 * kt][0],     acc[m][2 * kt][1],     pah[m][0], pal[m][0]);
                    split_pack(acc[m][2 * kt][2],     acc[m][2 * kt][3],     pah[m][1], pal[m][1]);
                    split_pack(acc[m][2 * kt + 1][0], acc[m][2 * kt + 1][1], pah[m][2], pal[m][2]);
                    split_pack(acc[m][2 * kt + 1][2], acc[m][2 * kt + 1][3], pah[m][3], pal[m][3]);
                }
                const int rV = kt * 16 + (lane & 15);
                const int gV = lane >> 4;
                #pragma unroll
                for (int np = 0; np < 4; np++) {
                    uint32_t vh[2][2], vl[2][2];
                    const int ch = np * 2 + gV;
                    uint32_t a0 = sk + 16384 + rV * 128 + ((ch ^ (rV & 7)) << 4);
                    asm volatile(
                        "ldmatrix.sync.aligned.m8n8.x4.trans.shared.b16 {%0,%1,%2,%3}, [%4];"
                        : "=r"(vh[0][0]), "=r"(vh[0][1]), "=r"(vh[1][0]), "=r"(vh[1][1])
                        : "r"(a0));
                    asm volatile(
                        "ldmatrix.sync.aligned.m8n8.x4.trans.shared.b16 {%0,%1,%2,%3}, [%4];"
                        : "=r"(vl[0][0]), "=r"(vl[0][1]), "=r"(vl[1][0]), "=r"(vl[1][1])
                        : "r"(a0 + 8192));
                    #pragma unroll
                    for (int nn = 0; nn < 2; nn++) {
                        const int n = np * 2 + nn;
                        #pragma unroll
                        for (int m = 0; m < 2; m++) {
                            if (m == 0 && skip0) continue;
                            mma_bf16(o[m][n], pah[m], vh[nn]);
                            mma_bf16(o[m][n], pal[m], vh[nn]);
                            mma_bf16(o[m][n], pah[m], vl[nn]);
                        }
                    }
                }
            }

            __syncthreads();
            if (kb + 2 < nkb) {
                attn_load_kv(smem_base + 32768 + (kb & 1) * 32768, tid, b, h0,
                             (kb + 2) * 64, qkvh, qkvl);
                CP_COMMIT();
            }
        }

        float inv[2][2];
        #pragma unroll
        for (int m = 0; m < 2; m++)
            #pragma unroll
            for (int h = 0; h < 2; h++) {
                float lt = lrow[m][h];
                lt += __shfl_xor_sync(0xffffffffu, lt, 1);
                lt += __shfl_xor_sync(0xffffffffu, lt, 2);
                inv[m][h] = 1.f / lt;
            }

        #pragma unroll
        for (int m = 0; m < 2; m++) {
            const int r0 = qbase + warp * 16 + m * 64 + (lane >> 2);
            #pragma unroll
            for (int n = 0; n < 8; n++) {
                const int cd = h0 * 64 + n * 8 + ((lane & 3) << 1);
                uint32_t h_, l_;
                split_pack(o[m][n][0] * inv[m][0], o[m][n][1] * inv[m][0], h_, l_);
                size_t base0 = (size_t)(b * TT + r0) * 1024 + cd;
                *(uint32_t*)(outh + base0) = h_;
                *(uint32_t*)(outl + base0) = l_;
                split_pack(o[m][n][2] * inv[m][1], o[m][n][3] * inv[m][1], h_, l_);
                size_t base1 = (size_t)(b * TT + r0 + 8) * 1024 + cd;
                *(uint32_t*)(outh + base1) = h_;
                *(uint32_t*)(outl + base1) = l_;
            }
        }
    }
}

// ---------------------------------------------------------------------------
extern "C" void kernel_launch(void* const* d_in, const int* in_sizes, int n_in,
                              void* d_out, int out_size)
{
    const float* x    = (const float*)d_in[0];
    const float* Wqkv = (const float*)d_in[1];
    const float* Wout = (const float*)d_in[2];
    float* out = (float*)d_out;

    __nv_bfloat16 *qkvh, *qkvl, *xh, *xl, *wqh, *wql, *woh, *wol, *ah, *al;
    cudaGetSymbolAddress((void**)&qkvh, g_qkvh); cudaGetSymbolAddress((void**)&qkvl, g_qkvl);
    cudaGetSymbolAddress((void**)&xh, g_xh);     cudaGetSymbolAddress((void**)&xl, g_xl);
    cudaGetSymbolAddress((void**)&wqh, g_wqh);   cudaGetSymbolAddress((void**)&wql, g_wql);
    cudaGetSymbolAddress((void**)&woh, g_woh);   cudaGetSymbolAddress((void**)&wol, g_wol);
    cudaGetSymbolAddress((void**)&ah, g_ah);     cudaGetSymbolAddress((void**)&al, g_al);

    cudaFuncSetAttribute(gemm_split_kernel,
                         cudaFuncAttributeMaxDynamicSharedMemorySize, 98304);
    cudaFuncSetAttribute(attn_mma_kernel,
                         cudaFuncAttributeMaxDynamicSharedMemorySize, 98304);

    const int M = TB * TT;            // 4096
    const int total4 = (NX + NWQ + NWO) / 4;

    // 0) fused input splits
    split3_kernel<<<(total4 + 255) / 256, 256>>>(x, Wqkv, Wout,
                                                 xh, xl, wqh, wql, woh, wol);

    // 1) QKV projection -> bf16 hi/lo planes (persistent, 768 tiles)
    {
        int tiles = (M / 128) * (3 * TC / 128);
        int grid = tiles < 296 ? tiles : 296;
        gemm_split_kernel<<<grid, 256, 98304>>>(
            xh, xl, wqh, wql, nullptr, qkvh, qkvl, M, 3 * TC, TC, 1);
    }

    // 2) Persistent causal flash attention -> bf16 hi/lo planes
    attn_mma_kernel<<<296, 128, 98304>>>(qkvh, qkvl, ah, al);

    // 3) Output projection -> fp32 out (256 tiles)
    {
        int tiles = (M / 128) * (TC / 128);
        int grid = tiles < 296 ? tiles : 296;
        gemm_split_kernel<<<grid, 256, 98304>>>(
            ah, al, woh, wol, out, nullptr, nullptr, M, TC, TC, 0);
    }
}